// round 4
// baseline (speedup 1.0000x reference)
#include <cuda_runtime.h>

// DeepAttensionModule — SeFT cumulative set attention.
//  k_feat : per-token psi/phi MLPs (2 threads/token, lane-pair split);
//           Wkq computed in-block; emits phi[32], a[4], xq[4]
//  k_scan : per (b,h) 1024-thread block: parallel online-softmax scan -> agg
//  k_rho  : rho MLP, 512 thr/block, 4-way output split, q4-interleaved weights

#define BATCH 16
#define SEQ   1024
#define NTOK  (BATCH*SEQ)
#define KEYIN 95
#define NEG_BIG (-3.402823466e38f)

__device__ float g_phi[NTOK*32];
__device__ float g_a[NTOK*4];
__device__ float g_xq[NTOK*4];
__device__ float g_agg[NTOK*128];

// ---------------------------------------------------------------- k_feat
// 256 threads, 128 tokens per block. Pair (2t, 2t+1) shares one token.
__global__ void __launch_bounds__(256) k_feat(
    const float* __restrict__ times, const float* __restrict__ values,
    const int*   __restrict__ meas,  const float* __restrict__ mask,
    const float* __restrict__ Wp1, const float* __restrict__ bp1,
    const float* __restrict__ Wp2, const float* __restrict__ bp2,
    const float* __restrict__ Wk,  const float* __restrict__ q,
    const float* __restrict__ Wf1, const float* __restrict__ bf1,
    const float* __restrict__ Wf2, const float* __restrict__ bf2)
{
    __shared__ float sWp1[9*64];
    __shared__ float sMp1[64*22];
    __shared__ float sWp2[64*64];
    __shared__ float sWf1[9*32];
    __shared__ float sMf1[32*22];
    __shared__ float sWf2[32*32];
    __shared__ float sWkq[KEYIN*4];
    __shared__ float sq[128];
    __shared__ float sbp1[64], sbp2[64], sbf1[32], sbf2[32];

    int tid = threadIdx.x;
    for (int i = tid; i < 9*64;  i += 256) sWp1[i] = Wp1[i];
    for (int i = tid; i < 64*22; i += 256) { int j = i/22, m = i%22; sMp1[i] = Wp1[(9+m)*64 + j]; }
    for (int i = tid; i < 64*64; i += 256) sWp2[i] = Wp2[i];
    for (int i = tid; i < 9*32;  i += 256) sWf1[i] = Wf1[i];
    for (int i = tid; i < 32*22; i += 256) { int j = i/22, m = i%22; sMf1[i] = Wf1[(9+m)*32 + j]; }
    for (int i = tid; i < 32*32; i += 256) sWf2[i] = Wf2[i];
    if (tid < 128) sq[tid] = q[tid];
    if (tid < 64) { sbp1[tid] = bp1[tid]; sbp2[tid] = bp2[tid]; }
    if (tid < 32) { sbf1[tid] = bf1[tid]; sbf2[tid] = bf2[tid]; }
    __syncthreads();
    // Wkq[s][h] = sum_d Wk[s][h*32+d] * q[h][d]
    for (int i = tid; i < KEYIN*4; i += 256) {
        int s = i >> 2, h = i & 3;
        float acc = 0.f;
        #pragma unroll
        for (int d = 0; d < 32; d++) acc += Wk[s*128 + h*32 + d] * sq[h*32 + d];
        sWkq[i] = acc;
    }
    __syncthreads();

    int tok  = tid >> 1;
    int half = tid & 1;
    int idx  = blockIdx.x*128 + tok;

    float t  = times[idx];
    float v  = values[idx];
    float mk = mask[idx];
    int   ms = meas[idx];

    float x9[9];
    x9[0] = sinf(t);          x9[1] = cosf(t);
    x9[2] = sinf(t*0.1f);     x9[3] = cosf(t*0.1f);
    x9[4] = sinf(t*0.01f);    x9[5] = cosf(t*0.01f);
    x9[6] = sinf(t*0.001f);   x9[7] = cosf(t*0.001f);
    x9[8] = v;

    const float4* sWp1v = (const float4*)sWp1;
    const float4* sWp2v = (const float4*)sWp2;
    const float4* sWf1v = (const float4*)sWf1;
    const float4* sWf2v = (const float4*)sWf2;
    const float4* sWkqv = (const float4*)sWkq;

    // ---- psi layer 1: this thread computes its 32-j half ----
    float hacc[32];
    #pragma unroll
    for (int jj = 0; jj < 32; jj++) hacc[jj] = sbp1[half*32 + jj];
    #pragma unroll
    for (int r = 0; r < 9; r++) {
        float s = x9[r];
        #pragma unroll
        for (int j4 = 0; j4 < 8; j4++) {
            float4 w = sWp1v[r*16 + half*8 + j4];
            hacc[j4*4+0] += s*w.x; hacc[j4*4+1] += s*w.y;
            hacc[j4*4+2] += s*w.z; hacc[j4*4+3] += s*w.w;
        }
    }
    if (ms > 0) {
        int m = ms - 1;
        #pragma unroll
        for (int jj = 0; jj < 32; jj++) hacc[jj] += sMp1[(half*32 + jj)*22 + m];
    }
    float hmine[32], hother[32];
    #pragma unroll
    for (int jj = 0; jj < 32; jj++) hmine[jj] = fmaxf(hacc[jj], 0.f);
    #pragma unroll
    for (int jj = 0; jj < 32; jj++) hother[jj] = __shfl_xor_sync(0xffffffffu, hmine[jj], 1);

    // ---- psi layer 2: outputs j in [half*32, half*32+32) over all 64 c ----
    float acc2[32];
    #pragma unroll
    for (int jj = 0; jj < 32; jj++) acc2[jj] = sbp2[half*32 + jj];
    int cm = half ? 32 : 0;   // c-range this thread computed
    int co = half ? 0  : 32;  // c-range from partner
    #pragma unroll 8
    for (int i = 0; i < 32; i++) {
        float s = hmine[i];
        #pragma unroll
        for (int j4 = 0; j4 < 8; j4++) {
            float4 w = sWp2v[(cm+i)*16 + half*8 + j4];
            acc2[j4*4+0] += s*w.x; acc2[j4*4+1] += s*w.y;
            acc2[j4*4+2] += s*w.z; acc2[j4*4+3] += s*w.w;
        }
    }
    #pragma unroll 8
    for (int i = 0; i < 32; i++) {
        float s = hother[i];
        #pragma unroll
        for (int j4 = 0; j4 < 8; j4++) {
            float4 w = sWp2v[(co+i)*16 + half*8 + j4];
            acc2[j4*4+0] += s*w.x; acc2[j4*4+1] += s*w.y;
            acc2[j4*4+2] += s*w.z; acc2[j4*4+3] += s*w.w;
        }
    }
    // a[4] partial over this thread's 32 j's, then pair-reduce
    float a0 = 0.f, a1 = 0.f, a2 = 0.f, a3 = 0.f;
    #pragma unroll
    for (int jj = 0; jj < 32; jj++) {
        float ps = fmaxf(acc2[jj], 0.f) * mk;
        float4 wk = sWkqv[31 + half*32 + jj];
        a0 += ps*wk.x; a1 += ps*wk.y; a2 += ps*wk.z; a3 += ps*wk.w;
    }
    a0 += __shfl_xor_sync(0xffffffffu, a0, 1);
    a1 += __shfl_xor_sync(0xffffffffu, a1, 1);
    a2 += __shfl_xor_sync(0xffffffffu, a2, 1);
    a3 += __shfl_xor_sync(0xffffffffu, a3, 1);
    if (half == 0) ((float4*)g_a)[idx] = make_float4(a0, a1, a2, a3);

    // ---- xq[4] = x·Wkq1 (cheap; even thread writes) ----
    {
        float q0 = 0.f, q1 = 0.f, q2 = 0.f, q3 = 0.f;
        #pragma unroll
        for (int r = 0; r < 9; r++) {
            float4 wk = sWkqv[r];
            q0 += x9[r]*wk.x; q1 += x9[r]*wk.y; q2 += x9[r]*wk.z; q3 += x9[r]*wk.w;
        }
        if (ms > 0) {
            float4 wk = sWkqv[8 + ms];
            q0 += wk.x; q1 += wk.y; q2 += wk.z; q3 += wk.w;
        }
        if (half == 0) ((float4*)g_xq)[idx] = make_float4(q0, q1, q2, q3);
    }

    // ---- phi layer 1: 16-j quarter each ----
    float facc[16];
    #pragma unroll
    for (int jj = 0; jj < 16; jj++) facc[jj] = sbf1[half*16 + jj];
    #pragma unroll
    for (int r = 0; r < 9; r++) {
        float s = x9[r];
        #pragma unroll
        for (int j4 = 0; j4 < 4; j4++) {
            float4 w = sWf1v[r*8 + half*4 + j4];
            facc[j4*4+0] += s*w.x; facc[j4*4+1] += s*w.y;
            facc[j4*4+2] += s*w.z; facc[j4*4+3] += s*w.w;
        }
    }
    if (ms > 0) {
        int m = ms - 1;
        #pragma unroll
        for (int jj = 0; jj < 16; jj++) facc[jj] += sMf1[(half*16 + jj)*22 + m];
    }
    float fmine[16], fother[16];
    #pragma unroll
    for (int jj = 0; jj < 16; jj++) fmine[jj] = fmaxf(facc[jj], 0.f);
    #pragma unroll
    for (int jj = 0; jj < 16; jj++) fother[jj] = __shfl_xor_sync(0xffffffffu, fmine[jj], 1);

    // ---- phi layer 2: outputs j in [half*16, half*16+16) ----
    float pacc[16];
    #pragma unroll
    for (int jj = 0; jj < 16; jj++) pacc[jj] = sbf2[half*16 + jj];
    int fm = half ? 16 : 0;
    int fo = half ? 0  : 16;
    #pragma unroll 8
    for (int i = 0; i < 16; i++) {
        float s = fmine[i];
        #pragma unroll
        for (int j4 = 0; j4 < 4; j4++) {
            float4 w = sWf2v[(fm+i)*8 + half*4 + j4];
            pacc[j4*4+0] += s*w.x; pacc[j4*4+1] += s*w.y;
            pacc[j4*4+2] += s*w.z; pacc[j4*4+3] += s*w.w;
        }
    }
    #pragma unroll 8
    for (int i = 0; i < 16; i++) {
        float s = fother[i];
        #pragma unroll
        for (int j4 = 0; j4 < 4; j4++) {
            float4 w = sWf2v[(fo+i)*8 + half*4 + j4];
            pacc[j4*4+0] += s*w.x; pacc[j4*4+1] += s*w.y;
            pacc[j4*4+2] += s*w.z; pacc[j4*4+3] += s*w.w;
        }
    }
    float4* phv = (float4*)(g_phi + (size_t)idx*32 + half*16);
    #pragma unroll
    for (int j4 = 0; j4 < 4; j4++) {
        phv[j4] = make_float4(fmaxf(pacc[j4*4+0],0.f)*mk, fmaxf(pacc[j4*4+1],0.f)*mk,
                              fmaxf(pacc[j4*4+2],0.f)*mk, fmaxf(pacc[j4*4+3],0.f)*mk);
    }
}

// ---------------------------------------------------------------- k_scan
// one 1024-thread block per (batch, head). warp = 32-token chunk, lane = phi channel.
__global__ void __launch_bounds__(1024) k_scan(const float* __restrict__ mask,
                                               const float* __restrict__ bk,
                                               const float* __restrict__ q) {
    int b = blockIdx.x >> 2;
    int h = blockIdx.x & 3;
    int tid  = threadIdx.x;
    int warp = tid >> 5;
    int lane = tid & 31;
    int base = b * SEQ;
    const float inv_sqrt = 0.17677669529663688f;

    __shared__ float spre[SEQ];
    __shared__ float smk[SEQ];
    __shared__ float wsumA[32], wsumM[32];
    __shared__ float cM[32], cS[32], cV[32*33];
    __shared__ float pM[32], pS[32], pV[32*33];
    __shared__ float sbq;

    if (tid == 0) {
        float acc = 0.f;
        #pragma unroll
        for (int d = 0; d < 32; d++) acc += bk[h*32 + d] * q[h*32 + d];
        sbq = acc;
    }

    // ---- phase 1: block inclusive scan of a and mask -> pre ----
    float a  = g_a [(base+tid)*4 + h];
    float mk = mask[ base+tid ];
    float xq = g_xq[(base+tid)*4 + h];

    float A = a, Sm = mk;
    #pragma unroll
    for (int d = 1; d < 32; d <<= 1) {
        float tA = __shfl_up_sync(0xffffffffu, A, d);
        float tS = __shfl_up_sync(0xffffffffu, Sm, d);
        if (lane >= d) { A += tA; Sm += tS; }
    }
    if (lane == 31) { wsumA[warp] = A; wsumM[warp] = Sm; }
    __syncthreads();
    if (warp == 0) {
        float xA = wsumA[lane], xS = wsumM[lane];
        #pragma unroll
        for (int d = 1; d < 32; d <<= 1) {
            float tA = __shfl_up_sync(0xffffffffu, xA, d);
            float tS = __shfl_up_sync(0xffffffffu, xS, d);
            if (lane >= d) { xA += tA; xS += tS; }
        }
        wsumA[lane] = xA; wsumM[lane] = xS;
    }
    __syncthreads();
    if (warp > 0) { A += wsumA[warp-1]; Sm += wsumM[warp-1]; }

    float pre = (xq + sbq + __fdividef(A, Sm)) * inv_sqrt;
    spre[tid] = pre;
    smk[tid]  = mk;
    __syncthreads();

    // ---- phase 2: per-warp chunk reduce (cache phi in registers) ----
    float ph[32];
    float M = NEG_BIG, S = 0.f, V = 0.f;
    int p0 = warp * 32;
    #pragma unroll
    for (int i = 0; i < 32; i++) {
        int p = p0 + i;
        float pr = spre[p];
        float f  = g_phi[(size_t)(base + p)*32 + lane];
        ph[i] = f;
        float nM = fmaxf(M, pr);
        float cs = __expf(M - nM);
        float w  = __expf(pr - nM);
        S = S*cs + w;
        V = V*cs + w*f;
        M = nM;
    }
    if (lane == 0) { cM[warp] = M; cS[warp] = S; }
    cV[warp*33 + lane] = V;
    __syncthreads();

    // ---- phase 3: warp 0 exclusive scan over 32 chunk summaries ----
    if (warp == 0) {
        float eM = NEG_BIG, eS = 0.f, eV = 0.f;
        #pragma unroll
        for (int c = 0; c < 32; c++) {
            if (lane == 0) { pM[c] = eM; pS[c] = eS; }
            pV[c*33 + lane] = eV;
            float m2 = cM[c], s2 = cS[c], v2 = cV[c*33 + lane];
            float nM = fmaxf(eM, m2);
            float e1 = __expf(eM - nM);
            float e2 = __expf(m2 - nM);
            eS = eS*e1 + s2*e2;
            eV = eV*e1 + v2*e2;
            eM = nM;
        }
    }
    __syncthreads();

    // ---- phase 4: replay chunk seeded with exclusive prefix ----
    M = pM[warp]; S = pS[warp]; V = pV[warp*33 + lane];
    #pragma unroll
    for (int i = 0; i < 32; i++) {
        int p = p0 + i;
        float pr = spre[p];
        float nM = fmaxf(M, pr);
        float cs = __expf(M - nM);
        float w  = __expf(pr - nM);
        S = S*cs + w;
        V = V*cs + w*ph[i];
        M = nM;
        g_agg[(size_t)(base + p)*128 + h*32 + lane] = __fdividef(V, S) * smk[p];
    }
}

// ---------------------------------------------------------------- k_rho
// 512 threads: 128 tokens x 4 output-quarters. tok = tid>>2, q4 = tid&3.
#define RHO_PAD 132
#define HH_PAD  68
#define W1_BS   2056   // 128*16 + 8  (block stride per q4; ≡8 mod 32 → conflict-free)
#define W2_BS   1032   // 64*16 + 8
extern __shared__ float rho_smem[];
__global__ void __launch_bounds__(512) k_rho(
    const float* __restrict__ W1, const float* __restrict__ b1,
    const float* __restrict__ W2, const float* __restrict__ b2,
    const float* __restrict__ mask, float* __restrict__ out)
{
    float* sW1 = rho_smem;                  // 4 * W1_BS
    float* sW2 = sW1 + 4*W1_BS;             // 4 * W2_BS
    float* sA  = sW2 + 4*W2_BS;             // 128*RHO_PAD (reused as sHH)
    float* sb1 = sA  + 128*RHO_PAD;
    float* sb2 = sb1 + 64;
    float* sHH = sA;

    int tid  = threadIdx.x;
    int tok  = tid >> 2;
    int q4   = tid & 3;
    int tok0 = blockIdx.x * 128;

    // stage weights, q4-interleaved: sW1[q][k*16 + jj] = W1[k*64 + q*16 + jj]
    for (int i = tid; i < 128*64; i += 512) {
        int k = i >> 6, j = i & 63;
        sW1[(j>>4)*W1_BS + k*16 + (j&15)] = W1[i];
    }
    for (int i = tid; i < 64*64; i += 512) {
        int c = i >> 6, j = i & 63;
        sW2[(j>>4)*W2_BS + c*16 + (j&15)] = W2[i];
    }
    if (tid < 64) { sb1[tid] = b1[tid]; sb2[tid] = b2[tid]; }
    {
        const float4* src = (const float4*)(g_agg + (size_t)tok0*128);
        #pragma unroll 8
        for (int l4 = tid; l4 < 128*32; l4 += 512) {
            int tk = l4 >> 5, k4 = l4 & 31;
            ((float4*)(sA + tk*RHO_PAD))[k4] = src[l4];
        }
    }
    __syncthreads();

    // ---- layer 1: 16 outputs over K=128 ----
    float acc[16];
    #pragma unroll
    for (int j = 0; j < 16; j++) acc[j] = 0.f;
    const float4* rowA = (const float4*)(sA + tok*RHO_PAD);
    const float4* w1q  = (const float4*)(sW1 + q4*W1_BS);
    #pragma unroll 4
    for (int k4 = 0; k4 < 32; k4++) {
        float4 xv = rowA[k4];
        #pragma unroll
        for (int e = 0; e < 4; e++) {
            float s = (e==0)?xv.x:(e==1)?xv.y:(e==2)?xv.z:xv.w;
            int k = k4*4 + e;
            #pragma unroll
            for (int j4 = 0; j4 < 4; j4++) {
                float4 w = w1q[k*4 + j4];
                acc[j4*4+0] += s*w.x; acc[j4*4+1] += s*w.y;
                acc[j4*4+2] += s*w.z; acc[j4*4+3] += s*w.w;
            }
        }
    }
    float hh[16];
    #pragma unroll
    for (int j = 0; j < 16; j++) hh[j] = fmaxf(acc[j] + sb1[q4*16 + j], 0.f);

    __syncthreads();   // all layer-1 act reads done before overwrite
    {
        float4* rowH = (float4*)(sHH + tok*HH_PAD);
        #pragma unroll
        for (int j4 = 0; j4 < 4; j4++)
            rowH[q4*4 + j4] = make_float4(hh[j4*4+0], hh[j4*4+1], hh[j4*4+2], hh[j4*4+3]);
    }
    __syncthreads();

    // ---- layer 2: 16 outputs over K=64 ----
    float acc2[16];
    #pragma unroll
    for (int j = 0; j < 16; j++) acc2[j] = sb2[q4*16 + j];
    const float4* rowH = (const float4*)(sHH + tok*HH_PAD);
    const float4* w2q  = (const float4*)(sW2 + q4*W2_BS);
    #pragma unroll 4
    for (int c4 = 0; c4 < 16; c4++) {
        float4 xv = rowH[c4];
        #pragma unroll
        for (int e = 0; e < 4; e++) {
            float s = (e==0)?xv.x:(e==1)?xv.y:(e==2)?xv.z:xv.w;
            int c = c4*4 + e;
            #pragma unroll
            for (int j4 = 0; j4 < 4; j4++) {
                float4 w = w2q[c*4 + j4];
                acc2[j4*4+0] += s*w.x; acc2[j4*4+1] += s*w.y;
                acc2[j4*4+2] += s*w.z; acc2[j4*4+3] += s*w.w;
            }
        }
    }
    float mk = mask[tok0 + tok];
    float4* op = (float4*)(out + (size_t)(tok0 + tok)*64 + q4*16);
    #pragma unroll
    for (int j4 = 0; j4 < 4; j4++) {
        op[j4] = make_float4(fmaxf(acc2[j4*4+0],0.f)*mk, fmaxf(acc2[j4*4+1],0.f)*mk,
                             fmaxf(acc2[j4*4+2],0.f)*mk, fmaxf(acc2[j4*4+3],0.f)*mk);
    }
}

// ---------------------------------------------------------------- launch
extern "C" void kernel_launch(void* const* d_in, const int* in_sizes, int n_in,
                              void* d_out, int out_size) {
    (void)in_sizes; (void)n_in; (void)out_size;
    const float* times  = (const float*)d_in[0];
    const float* values = (const float*)d_in[1];
    const int*   meas   = (const int*)  d_in[2];
    const float* mask   = (const float*)d_in[3];
    const float* Wp1 = (const float*)d_in[4];  const float* bp1 = (const float*)d_in[5];
    const float* Wp2 = (const float*)d_in[6];  const float* bp2 = (const float*)d_in[7];
    const float* Wk  = (const float*)d_in[8];  const float* bk  = (const float*)d_in[9];
    const float* q   = (const float*)d_in[10];
    const float* Wf1 = (const float*)d_in[11]; const float* bf1 = (const float*)d_in[12];
    const float* Wf2 = (const float*)d_in[13]; const float* bf2 = (const float*)d_in[14];
    const float* Wr1 = (const float*)d_in[15]; const float* br1 = (const float*)d_in[16];
    const float* Wr2 = (const float*)d_in[17]; const float* br2 = (const float*)d_in[18];
    float* out = (float*)d_out;

    size_t rho_bytes = (4*W1_BS + 4*W2_BS + 128*RHO_PAD + 128) * sizeof(float);
    cudaFuncSetAttribute(k_rho, cudaFuncAttributeMaxDynamicSharedMemorySize, (int)rho_bytes);

    k_feat<<<128, 256>>>(times, values, meas, mask,
                         Wp1, bp1, Wp2, bp2, Wk, q, Wf1, bf1, Wf2, bf2);
    k_scan<<<BATCH*4, 1024>>>(mask, bk, q);
    k_rho<<<128, 512, rho_bytes>>>(Wr1, br1, Wr2, br2, mask, out);
}

// round 5
// speedup vs baseline: 1.5834x; 1.5834x over previous
#include <cuda_runtime.h>

// DeepAttensionModule — SeFT cumulative set attention.
//  k_feat : per-token psi/phi MLPs, 1 thread/token (broadcast smem weights);
//           Wkq folded in-block; emits phi[32], a[4], xq[4]
//  k_scan : per (b,h) 1024-thread block: parallel online-softmax scan -> agg
//  k_rho  : rho MLP, 512 thr/block, 4-way output split, q4-interleaved weights

#define BATCH 16
#define SEQ   1024
#define NTOK  (BATCH*SEQ)
#define KEYIN 95
#define NEG_BIG (-3.402823466e38f)

__device__ float g_phi[NTOK*32];
__device__ float g_a[NTOK*4];
__device__ float g_xq[NTOK*4];
__device__ float g_agg[NTOK*128];

// ---------------------------------------------------------------- k_feat
__global__ void __launch_bounds__(128) k_feat(
    const float* __restrict__ times, const float* __restrict__ values,
    const int*   __restrict__ meas,  const float* __restrict__ mask,
    const float* __restrict__ Wp1, const float* __restrict__ bp1,
    const float* __restrict__ Wp2, const float* __restrict__ bp2,
    const float* __restrict__ Wk,  const float* __restrict__ q,
    const float* __restrict__ Wf1, const float* __restrict__ bf1,
    const float* __restrict__ Wf2, const float* __restrict__ bf2)
{
    __shared__ float sWp1[9*64];
    __shared__ float sMp1[64*22];
    __shared__ float sWp2[64*64];
    __shared__ float sWf1[9*32];
    __shared__ float sMf1[32*22];
    __shared__ float sWf2[32*32];
    __shared__ float sWkq[KEYIN*4];
    __shared__ float sq[128];
    __shared__ float sbp1[64], sbp2[64], sbf1[32], sbf2[32];

    int tid = threadIdx.x;
    for (int i = tid; i < 9*64;  i += 128) sWp1[i] = Wp1[i];
    for (int i = tid; i < 64*22; i += 128) { int j = i/22, m = i%22; sMp1[i] = Wp1[(9+m)*64 + j]; }
    for (int i = tid; i < 64*64; i += 128) sWp2[i] = Wp2[i];
    for (int i = tid; i < 9*32;  i += 128) sWf1[i] = Wf1[i];
    for (int i = tid; i < 32*22; i += 128) { int j = i/22, m = i%22; sMf1[i] = Wf1[(9+m)*32 + j]; }
    for (int i = tid; i < 32*32; i += 128) sWf2[i] = Wf2[i];
    if (tid < 128) sq[tid] = q[tid];
    if (tid < 64) { sbp1[tid] = bp1[tid]; sbp2[tid] = bp2[tid]; }
    if (tid < 32) { sbf1[tid] = bf1[tid]; sbf2[tid] = bf2[tid]; }
    __syncthreads();
    // Wkq[s][h] = sum_d Wk[s][h*32+d] * q[h][d]
    for (int i = tid; i < KEYIN*4; i += 128) {
        int s = i >> 2, h = i & 3;
        float acc = 0.f;
        #pragma unroll
        for (int d = 0; d < 32; d++) acc += Wk[s*128 + h*32 + d] * sq[h*32 + d];
        sWkq[i] = acc;
    }
    __syncthreads();

    int idx = blockIdx.x*128 + tid;
    float t  = times[idx];
    float v  = values[idx];
    float mk = mask[idx];
    int   ms = meas[idx];

    float x9[9];
    x9[0] = sinf(t);          x9[1] = cosf(t);
    x9[2] = sinf(t*0.1f);     x9[3] = cosf(t*0.1f);
    x9[4] = sinf(t*0.01f);    x9[5] = cosf(t*0.01f);
    x9[6] = sinf(t*0.001f);   x9[7] = cosf(t*0.001f);
    x9[8] = v;

    // ---- psi layer 1 ----
    float acc[64];
    #pragma unroll
    for (int j = 0; j < 64; j++) acc[j] = sbp1[j];
    const float4* sWp1v = (const float4*)sWp1;
    #pragma unroll
    for (int r = 0; r < 9; r++) {
        float s = x9[r];
        #pragma unroll
        for (int j4 = 0; j4 < 16; j4++) {
            float4 w = sWp1v[r*16 + j4];
            acc[j4*4+0] += s*w.x; acc[j4*4+1] += s*w.y;
            acc[j4*4+2] += s*w.z; acc[j4*4+3] += s*w.w;
        }
    }
    if (ms > 0) {
        int m = ms - 1;
        #pragma unroll
        for (int j = 0; j < 64; j++) acc[j] += sMp1[j*22 + m];
    }
    float h1[64];
    #pragma unroll
    for (int j = 0; j < 64; j++) h1[j] = fmaxf(acc[j], 0.f);

    // ---- psi layer 2 folded into a[4] = (psi*m)·Wkq2 ----
    #pragma unroll
    for (int j = 0; j < 64; j++) acc[j] = sbp2[j];
    const float4* sWp2v = (const float4*)sWp2;
    #pragma unroll 8
    for (int c = 0; c < 64; c++) {
        float s = h1[c];
        #pragma unroll
        for (int j4 = 0; j4 < 16; j4++) {
            float4 w = sWp2v[c*16 + j4];
            acc[j4*4+0] += s*w.x; acc[j4*4+1] += s*w.y;
            acc[j4*4+2] += s*w.z; acc[j4*4+3] += s*w.w;
        }
    }
    const float4* sWkqv = (const float4*)sWkq;
    float a0 = 0.f, a1 = 0.f, a2 = 0.f, a3 = 0.f;
    #pragma unroll
    for (int j = 0; j < 64; j++) {
        float ps = fmaxf(acc[j], 0.f) * mk;
        float4 wk = sWkqv[31 + j];
        a0 += ps*wk.x; a1 += ps*wk.y; a2 += ps*wk.z; a3 += ps*wk.w;
    }
    ((float4*)g_a)[idx] = make_float4(a0, a1, a2, a3);

    // ---- xq[4] = x·Wkq1 ----
    float q0 = 0.f, q1 = 0.f, q2 = 0.f, q3 = 0.f;
    #pragma unroll
    for (int r = 0; r < 9; r++) {
        float4 wk = sWkqv[r];
        q0 += x9[r]*wk.x; q1 += x9[r]*wk.y; q2 += x9[r]*wk.z; q3 += x9[r]*wk.w;
    }
    if (ms > 0) {
        float4 wk = sWkqv[8 + ms];
        q0 += wk.x; q1 += wk.y; q2 += wk.z; q3 += wk.w;
    }
    ((float4*)g_xq)[idx] = make_float4(q0, q1, q2, q3);

    // ---- phi MLP ----
    float f1[32];
    {
        float fa[32];
        #pragma unroll
        for (int j = 0; j < 32; j++) fa[j] = sbf1[j];
        const float4* sWf1v = (const float4*)sWf1;
        #pragma unroll
        for (int r = 0; r < 9; r++) {
            float s = x9[r];
            #pragma unroll
            for (int j4 = 0; j4 < 8; j4++) {
                float4 w = sWf1v[r*8 + j4];
                fa[j4*4+0] += s*w.x; fa[j4*4+1] += s*w.y;
                fa[j4*4+2] += s*w.z; fa[j4*4+3] += s*w.w;
            }
        }
        if (ms > 0) {
            int m = ms - 1;
            #pragma unroll
            for (int j = 0; j < 32; j++) fa[j] += sMf1[j*22 + m];
        }
        #pragma unroll
        for (int j = 0; j < 32; j++) f1[j] = fmaxf(fa[j], 0.f);
    }
    {
        float fa[32];
        #pragma unroll
        for (int j = 0; j < 32; j++) fa[j] = sbf2[j];
        const float4* sWf2v = (const float4*)sWf2;
        #pragma unroll 8
        for (int c = 0; c < 32; c++) {
            float s = f1[c];
            #pragma unroll
            for (int j4 = 0; j4 < 8; j4++) {
                float4 w = sWf2v[c*8 + j4];
                fa[j4*4+0] += s*w.x; fa[j4*4+1] += s*w.y;
                fa[j4*4+2] += s*w.z; fa[j4*4+3] += s*w.w;
            }
        }
        float4* phv = (float4*)(g_phi + (size_t)idx*32);
        #pragma unroll
        for (int j4 = 0; j4 < 8; j4++) {
            phv[j4] = make_float4(fmaxf(fa[j4*4+0],0.f)*mk, fmaxf(fa[j4*4+1],0.f)*mk,
                                  fmaxf(fa[j4*4+2],0.f)*mk, fmaxf(fa[j4*4+3],0.f)*mk);
        }
    }
}

// ---------------------------------------------------------------- k_scan
// one 1024-thread block per (batch, head). warp = 32-token chunk, lane = phi channel.
__global__ void __launch_bounds__(1024) k_scan(const float* __restrict__ mask,
                                               const float* __restrict__ bk,
                                               const float* __restrict__ q) {
    int b = blockIdx.x >> 2;
    int h = blockIdx.x & 3;
    int tid  = threadIdx.x;
    int warp = tid >> 5;
    int lane = tid & 31;
    int base = b * SEQ;
    const float inv_sqrt = 0.17677669529663688f;

    __shared__ float spre[SEQ];
    __shared__ float smk[SEQ];
    __shared__ float wsumA[32], wsumM[32];
    __shared__ float cM[32], cS[32], cV[32*33];
    __shared__ float pM[32], pS[32], pV[32*33];
    __shared__ float sbq;

    if (tid == 0) {
        float acc = 0.f;
        #pragma unroll
        for (int d = 0; d < 32; d++) acc += bk[h*32 + d] * q[h*32 + d];
        sbq = acc;
    }

    // ---- phase 1: block inclusive scan of a and mask -> pre ----
    float a  = g_a [(base+tid)*4 + h];
    float mk = mask[ base+tid ];
    float xq = g_xq[(base+tid)*4 + h];

    float A = a, Sm = mk;
    #pragma unroll
    for (int d = 1; d < 32; d <<= 1) {
        float tA = __shfl_up_sync(0xffffffffu, A, d);
        float tS = __shfl_up_sync(0xffffffffu, Sm, d);
        if (lane >= d) { A += tA; Sm += tS; }
    }
    if (lane == 31) { wsumA[warp] = A; wsumM[warp] = Sm; }
    __syncthreads();
    if (warp == 0) {
        float xA = wsumA[lane], xS = wsumM[lane];
        #pragma unroll
        for (int d = 1; d < 32; d <<= 1) {
            float tA = __shfl_up_sync(0xffffffffu, xA, d);
            float tS = __shfl_up_sync(0xffffffffu, xS, d);
            if (lane >= d) { xA += tA; xS += tS; }
        }
        wsumA[lane] = xA; wsumM[lane] = xS;
    }
    __syncthreads();
    if (warp > 0) { A += wsumA[warp-1]; Sm += wsumM[warp-1]; }

    float pre = (xq + sbq + __fdividef(A, Sm)) * inv_sqrt;
    spre[tid] = pre;
    smk[tid]  = mk;
    __syncthreads();

    // ---- phase 2: per-warp chunk reduce (cache phi in registers) ----
    float ph[32];
    float M = NEG_BIG, S = 0.f, V = 0.f;
    int p0 = warp * 32;
    #pragma unroll
    for (int i = 0; i < 32; i++) {
        int p = p0 + i;
        float pr = spre[p];
        float f  = g_phi[(size_t)(base + p)*32 + lane];
        ph[i] = f;
        float nM = fmaxf(M, pr);
        float cs = __expf(M - nM);
        float w  = __expf(pr - nM);
        S = S*cs + w;
        V = V*cs + w*f;
        M = nM;
    }
    if (lane == 0) { cM[warp] = M; cS[warp] = S; }
    cV[warp*33 + lane] = V;
    __syncthreads();

    // ---- phase 3: warp 0 exclusive scan over 32 chunk summaries ----
    if (warp == 0) {
        float eM = NEG_BIG, eS = 0.f, eV = 0.f;
        #pragma unroll
        for (int c = 0; c < 32; c++) {
            if (lane == 0) { pM[c] = eM; pS[c] = eS; }
            pV[c*33 + lane] = eV;
            float m2 = cM[c], s2 = cS[c], v2 = cV[c*33 + lane];
            float nM = fmaxf(eM, m2);
            float e1 = __expf(eM - nM);
            float e2 = __expf(m2 - nM);
            eS = eS*e1 + s2*e2;
            eV = eV*e1 + v2*e2;
            eM = nM;
        }
    }
    __syncthreads();

    // ---- phase 4: replay chunk seeded with exclusive prefix ----
    M = pM[warp]; S = pS[warp]; V = pV[warp*33 + lane];
    #pragma unroll
    for (int i = 0; i < 32; i++) {
        int p = p0 + i;
        float pr = spre[p];
        float nM = fmaxf(M, pr);
        float cs = __expf(M - nM);
        float w  = __expf(pr - nM);
        S = S*cs + w;
        V = V*cs + w*ph[i];
        M = nM;
        g_agg[(size_t)(base + p)*128 + h*32 + lane] = __fdividef(V, S) * smk[p];
    }
}

// ---------------------------------------------------------------- k_rho
// 512 threads: 128 tokens x 4 output-quarters. tok = tid>>2, q4 = tid&3.
#define RHO_PAD 132
#define HH_PAD  68
#define W1_BS   2056   // 128*16 + 8  (block stride per q4; ≡8 mod 32 → conflict-free)
#define W2_BS   1032   // 64*16 + 8
extern __shared__ float rho_smem[];
__global__ void __launch_bounds__(512) k_rho(
    const float* __restrict__ W1, const float* __restrict__ b1,
    const float* __restrict__ W2, const float* __restrict__ b2,
    const float* __restrict__ mask, float* __restrict__ out)
{
    float* sW1 = rho_smem;                  // 4 * W1_BS
    float* sW2 = sW1 + 4*W1_BS;             // 4 * W2_BS
    float* sA  = sW2 + 4*W2_BS;             // 128*RHO_PAD (reused as sHH)
    float* sb1 = sA  + 128*RHO_PAD;
    float* sb2 = sb1 + 64;
    float* sHH = sA;

    int tid  = threadIdx.x;
    int tok  = tid >> 2;
    int q4   = tid & 3;
    int tok0 = blockIdx.x * 128;

    // stage weights, q4-interleaved: sW1[q][k*16 + jj] = W1[k*64 + q*16 + jj]
    for (int i = tid; i < 128*64; i += 512) {
        int k = i >> 6, j = i & 63;
        sW1[(j>>4)*W1_BS + k*16 + (j&15)] = W1[i];
    }
    for (int i = tid; i < 64*64; i += 512) {
        int c = i >> 6, j = i & 63;
        sW2[(j>>4)*W2_BS + c*16 + (j&15)] = W2[i];
    }
    if (tid < 64) { sb1[tid] = b1[tid]; sb2[tid] = b2[tid]; }
    {
        const float4* src = (const float4*)(g_agg + (size_t)tok0*128);
        #pragma unroll 8
        for (int l4 = tid; l4 < 128*32; l4 += 512) {
            int tk = l4 >> 5, k4 = l4 & 31;
            ((float4*)(sA + tk*RHO_PAD))[k4] = src[l4];
        }
    }
    __syncthreads();

    // ---- layer 1: 16 outputs over K=128 ----
    float acc[16];
    #pragma unroll
    for (int j = 0; j < 16; j++) acc[j] = 0.f;
    const float4* rowA = (const float4*)(sA + tok*RHO_PAD);
    const float4* w1q  = (const float4*)(sW1 + q4*W1_BS);
    #pragma unroll 4
    for (int k4 = 0; k4 < 32; k4++) {
        float4 xv = rowA[k4];
        #pragma unroll
        for (int e = 0; e < 4; e++) {
            float s = (e==0)?xv.x:(e==1)?xv.y:(e==2)?xv.z:xv.w;
            int k = k4*4 + e;
            #pragma unroll
            for (int j4 = 0; j4 < 4; j4++) {
                float4 w = w1q[k*4 + j4];
                acc[j4*4+0] += s*w.x; acc[j4*4+1] += s*w.y;
                acc[j4*4+2] += s*w.z; acc[j4*4+3] += s*w.w;
            }
        }
    }
    float hh[16];
    #pragma unroll
    for (int j = 0; j < 16; j++) hh[j] = fmaxf(acc[j] + sb1[q4*16 + j], 0.f);

    __syncthreads();   // all layer-1 act reads done before overwrite
    {
        float4* rowH = (float4*)(sHH + tok*HH_PAD);
        #pragma unroll
        for (int j4 = 0; j4 < 4; j4++)
            rowH[q4*4 + j4] = make_float4(hh[j4*4+0], hh[j4*4+1], hh[j4*4+2], hh[j4*4+3]);
    }
    __syncthreads();

    // ---- layer 2: 16 outputs over K=64 ----
    float acc2[16];
    #pragma unroll
    for (int j = 0; j < 16; j++) acc2[j] = sb2[q4*16 + j];
    const float4* rowH = (const float4*)(sHH + tok*HH_PAD);
    const float4* w2q  = (const float4*)(sW2 + q4*W2_BS);
    #pragma unroll 4
    for (int c4 = 0; c4 < 16; c4++) {
        float4 xv = rowH[c4];
        #pragma unroll
        for (int e = 0; e < 4; e++) {
            float s = (e==0)?xv.x:(e==1)?xv.y:(e==2)?xv.z:xv.w;
            int c = c4*4 + e;
            #pragma unroll
            for (int j4 = 0; j4 < 4; j4++) {
                float4 w = w2q[c*4 + j4];
                acc2[j4*4+0] += s*w.x; acc2[j4*4+1] += s*w.y;
                acc2[j4*4+2] += s*w.z; acc2[j4*4+3] += s*w.w;
            }
        }
    }
    float mk = mask[tok0 + tok];
    float4* op = (float4*)(out + (size_t)(tok0 + tok)*64 + q4*16);
    #pragma unroll
    for (int j4 = 0; j4 < 4; j4++) {
        op[j4] = make_float4(fmaxf(acc2[j4*4+0],0.f)*mk, fmaxf(acc2[j4*4+1],0.f)*mk,
                             fmaxf(acc2[j4*4+2],0.f)*mk, fmaxf(acc2[j4*4+3],0.f)*mk);
    }
}

// ---------------------------------------------------------------- launch
extern "C" void kernel_launch(void* const* d_in, const int* in_sizes, int n_in,
                              void* d_out, int out_size) {
    (void)in_sizes; (void)n_in; (void)out_size;
    const float* times  = (const float*)d_in[0];
    const float* values = (const float*)d_in[1];
    const int*   meas   = (const int*)  d_in[2];
    const float* mask   = (const float*)d_in[3];
    const float* Wp1 = (const float*)d_in[4];  const float* bp1 = (const float*)d_in[5];
    const float* Wp2 = (const float*)d_in[6];  const float* bp2 = (const float*)d_in[7];
    const float* Wk  = (const float*)d_in[8];  const float* bk  = (const float*)d_in[9];
    const float* q   = (const float*)d_in[10];
    const float* Wf1 = (const float*)d_in[11]; const float* bf1 = (const float*)d_in[12];
    const float* Wf2 = (const float*)d_in[13]; const float* bf2 = (const float*)d_in[14];
    const float* Wr1 = (const float*)d_in[15]; const float* br1 = (const float*)d_in[16];
    const float* Wr2 = (const float*)d_in[17]; const float* br2 = (const float*)d_in[18];
    float* out = (float*)d_out;

    size_t rho_bytes = (4*W1_BS + 4*W2_BS + 128*RHO_PAD + 128) * sizeof(float);
    cudaFuncSetAttribute(k_rho, cudaFuncAttributeMaxDynamicSharedMemorySize, (int)rho_bytes);

    k_feat<<<128, 128>>>(times, values, meas, mask,
                         Wp1, bp1, Wp2, bp2, Wk, q, Wf1, bf1, Wf2, bf2);
    k_scan<<<BATCH*4, 1024>>>(mask, bk, q);
    k_rho<<<128, 512, rho_bytes>>>(Wr1, br1, Wr2, br2, mask, out);
}

// round 6
// speedup vs baseline: 1.5889x; 1.0035x over previous
#include <cuda_runtime.h>

// DeepAttensionModule — SeFT cumulative set attention.
//  k_feat : 256 thr/block, 128 tokens; warp-role split (half = output channels),
//           lanes = tokens (weights broadcast); chunked psi to cap registers.
//  k_scan : per (b,h) 1024-thread block: parallel online-softmax scan -> agg
//  k_rho  : rho MLP, 512 thr/block, 4-way output split, q4-interleaved weights

#define BATCH 16
#define SEQ   1024
#define NTOK  (BATCH*SEQ)
#define KEYIN 95
#define NEG_BIG (-3.402823466e38f)

__device__ float g_phi[NTOK*32];
__device__ float g_a[NTOK*4];
__device__ float g_xq[NTOK*4];
__device__ float g_agg[NTOK*128];

// ---------------------------------------------------------------- k_feat
__global__ void __launch_bounds__(256) k_feat(
    const float* __restrict__ times, const float* __restrict__ values,
    const int*   __restrict__ meas,  const float* __restrict__ mask,
    const float* __restrict__ Wp1, const float* __restrict__ bp1,
    const float* __restrict__ Wp2, const float* __restrict__ bp2,
    const float* __restrict__ Wk,  const float* __restrict__ q,
    const float* __restrict__ Wf1, const float* __restrict__ bf1,
    const float* __restrict__ Wf2, const float* __restrict__ bf2)
{
    __shared__ float sWp1[9*64];
    __shared__ float sMp1[64*22];
    __shared__ float sWp2[64*64];
    __shared__ float sWf1[9*32];
    __shared__ float sMf1[32*22];
    __shared__ float sWf2[32*32];
    __shared__ float sWkq[KEYIN*4 + 4];
    __shared__ float sq[128];
    __shared__ float sbp1[64], sbp2[64], sbf1[32], sbf2[32];
    __shared__ float sPa[2*128*4];           // per-half partial a4

    int tid = threadIdx.x;
    if (tid < 128) sq[tid] = q[tid];
    for (int i = tid; i < 9*64;  i += 256) sWp1[i] = Wp1[i];
    for (int i = tid; i < 64*22; i += 256) { int j = i/22, m = i%22; sMp1[i] = Wp1[(9+m)*64 + j]; }
    for (int i = tid; i < 64*64; i += 256) sWp2[i] = Wp2[i];
    for (int i = tid; i < 9*32;  i += 256) sWf1[i] = Wf1[i];
    for (int i = tid; i < 32*22; i += 256) { int j = i/22, m = i%22; sMf1[i] = Wf1[(9+m)*32 + j]; }
    for (int i = tid; i < 32*32; i += 256) sWf2[i] = Wf2[i];
    if (tid < 64) { sbp1[tid] = bp1[tid]; sbp2[tid] = bp2[tid]; }
    if (tid < 32) { sbf1[tid] = bf1[tid]; sbf2[tid] = bf2[tid]; }
    __syncthreads();
    // Wkq[s][h] = sum_d Wk[s][h*32+d] * q[h][d]
    for (int i = tid; i < KEYIN*4; i += 256) {
        int s = i >> 2, h = i & 3;
        float acc = 0.f;
        #pragma unroll
        for (int d = 0; d < 32; d++) acc += Wk[s*128 + h*32 + d] * sq[h*32 + d];
        sWkq[i] = acc;
    }
    __syncthreads();

    int warp = tid >> 5, lane = tid & 31;
    int half = warp >> 2;                    // output-channel half (0/1)
    int tok  = (warp & 3) * 32 + lane;       // token within block
    int idx  = blockIdx.x*128 + tok;

    float t  = times[idx];
    float v  = values[idx];
    float mk = mask[idx];
    int   ms = meas[idx];

    float x9[9];
    x9[0] = sinf(t);          x9[1] = cosf(t);
    x9[2] = sinf(t*0.1f);     x9[3] = cosf(t*0.1f);
    x9[4] = sinf(t*0.01f);    x9[5] = cosf(t*0.01f);
    x9[6] = sinf(t*0.001f);   x9[7] = cosf(t*0.001f);
    x9[8] = v;

    const float4* sWp1v = (const float4*)sWp1;
    const float4* sWp2v = (const float4*)sWp2;
    const float4* sWf1v = (const float4*)sWf1;
    const float4* sWf2v = (const float4*)sWf2;
    const float4* sWkqv = (const float4*)sWkq;
    int m = ms - 1;

    // ---- psi: outputs j in [half*32, half*32+32), h1 consumed in 32-chunks ----
    float acc2[32];
    #pragma unroll
    for (int jj = 0; jj < 32; jj++) acc2[jj] = sbp2[half*32 + jj];

    #pragma unroll
    for (int chunk = 0; chunk < 2; chunk++) {
        float h1c[32];
        #pragma unroll
        for (int jj = 0; jj < 32; jj++) h1c[jj] = sbp1[chunk*32 + jj];
        #pragma unroll
        for (int r = 0; r < 9; r++) {
            float s = x9[r];
            #pragma unroll
            for (int j4 = 0; j4 < 8; j4++) {
                float4 w = sWp1v[r*16 + chunk*8 + j4];
                h1c[j4*4+0] += s*w.x; h1c[j4*4+1] += s*w.y;
                h1c[j4*4+2] += s*w.z; h1c[j4*4+3] += s*w.w;
            }
        }
        if (ms > 0) {
            #pragma unroll
            for (int jj = 0; jj < 32; jj++) h1c[jj] += sMp1[(chunk*32 + jj)*22 + m];
        }
        #pragma unroll
        for (int jj = 0; jj < 32; jj++) h1c[jj] = fmaxf(h1c[jj], 0.f);

        // psi2 partial over these 32 c's
        #pragma unroll 8
        for (int i = 0; i < 32; i++) {
            float s = h1c[i];
            int c = chunk*32 + i;
            #pragma unroll
            for (int j4 = 0; j4 < 8; j4++) {
                float4 w = sWp2v[c*16 + half*8 + j4];
                acc2[j4*4+0] += s*w.x; acc2[j4*4+1] += s*w.y;
                acc2[j4*4+2] += s*w.z; acc2[j4*4+3] += s*w.w;
            }
        }
    }
    // a4 partial over this half's 32 j's
    {
        float a0 = 0.f, a1 = 0.f, a2 = 0.f, a3 = 0.f;
        #pragma unroll
        for (int jj = 0; jj < 32; jj++) {
            float ps = fmaxf(acc2[jj], 0.f) * mk;
            float4 wk = sWkqv[31 + half*32 + jj];
            a0 += ps*wk.x; a1 += ps*wk.y; a2 += ps*wk.z; a3 += ps*wk.w;
        }
        ((float4*)sPa)[half*128 + tok] = make_float4(a0, a1, a2, a3);
    }

    // ---- phi: outputs j in [half*16, half*16+16), f1 consumed in 16-chunks ----
    float pacc[16];
    #pragma unroll
    for (int jj = 0; jj < 16; jj++) pacc[jj] = sbf2[half*16 + jj];

    #pragma unroll
    for (int chunk = 0; chunk < 2; chunk++) {
        float f1c[16];
        #pragma unroll
        for (int jj = 0; jj < 16; jj++) f1c[jj] = sbf1[chunk*16 + jj];
        #pragma unroll
        for (int r = 0; r < 9; r++) {
            float s = x9[r];
            #pragma unroll
            for (int j4 = 0; j4 < 4; j4++) {
                float4 w = sWf1v[r*8 + chunk*4 + j4];
                f1c[j4*4+0] += s*w.x; f1c[j4*4+1] += s*w.y;
                f1c[j4*4+2] += s*w.z; f1c[j4*4+3] += s*w.w;
            }
        }
        if (ms > 0) {
            #pragma unroll
            for (int jj = 0; jj < 16; jj++) f1c[jj] += sMf1[(chunk*16 + jj)*22 + m];
        }
        #pragma unroll
        for (int jj = 0; jj < 16; jj++) f1c[jj] = fmaxf(f1c[jj], 0.f);

        #pragma unroll 8
        for (int i = 0; i < 16; i++) {
            float s = f1c[i];
            int c = chunk*16 + i;
            #pragma unroll
            for (int j4 = 0; j4 < 4; j4++) {
                float4 w = sWf2v[c*8 + half*4 + j4];
                pacc[j4*4+0] += s*w.x; pacc[j4*4+1] += s*w.y;
                pacc[j4*4+2] += s*w.z; pacc[j4*4+3] += s*w.w;
            }
        }
    }
    {
        float4* phv = (float4*)(g_phi + (size_t)idx*32 + half*16);
        #pragma unroll
        for (int j4 = 0; j4 < 4; j4++)
            phv[j4] = make_float4(fmaxf(pacc[j4*4+0],0.f)*mk, fmaxf(pacc[j4*4+1],0.f)*mk,
                                  fmaxf(pacc[j4*4+2],0.f)*mk, fmaxf(pacc[j4*4+3],0.f)*mk);
    }

    __syncthreads();
    if (half == 0) {
        // combine a4 halves
        float4 pa = ((float4*)sPa)[tok];
        float4 pb = ((float4*)sPa)[128 + tok];
        ((float4*)g_a)[idx] = make_float4(pa.x+pb.x, pa.y+pb.y, pa.z+pb.z, pa.w+pb.w);
        // xq[4] = x·Wkq1
        float q0 = 0.f, q1 = 0.f, q2 = 0.f, q3 = 0.f;
        #pragma unroll
        for (int r = 0; r < 9; r++) {
            float4 wk = sWkqv[r];
            q0 += x9[r]*wk.x; q1 += x9[r]*wk.y; q2 += x9[r]*wk.z; q3 += x9[r]*wk.w;
        }
        if (ms > 0) {
            float4 wk = sWkqv[8 + ms];
            q0 += wk.x; q1 += wk.y; q2 += wk.z; q3 += wk.w;
        }
        ((float4*)g_xq)[idx] = make_float4(q0, q1, q2, q3);
    }
}

// ---------------------------------------------------------------- k_scan
// one 1024-thread block per (batch, head). warp = 32-token chunk, lane = phi channel.
__global__ void __launch_bounds__(1024) k_scan(const float* __restrict__ mask,
                                               const float* __restrict__ bk,
                                               const float* __restrict__ q) {
    int b = blockIdx.x >> 2;
    int h = blockIdx.x & 3;
    int tid  = threadIdx.x;
    int warp = tid >> 5;
    int lane = tid & 31;
    int base = b * SEQ;
    const float inv_sqrt = 0.17677669529663688f;

    __shared__ float spre[SEQ];
    __shared__ float smk[SEQ];
    __shared__ float wsumA[32], wsumM[32];
    __shared__ float cM[32], cS[32], cV[32*33];
    __shared__ float pM[32], pS[32], pV[32*33];
    __shared__ float sbq;

    if (tid == 0) {
        float acc = 0.f;
        #pragma unroll
        for (int d = 0; d < 32; d++) acc += bk[h*32 + d] * q[h*32 + d];
        sbq = acc;
    }

    // ---- phase 1: block inclusive scan of a and mask -> pre ----
    float a  = g_a [(base+tid)*4 + h];
    float mk = mask[ base+tid ];
    float xq = g_xq[(base+tid)*4 + h];

    float A = a, Sm = mk;
    #pragma unroll
    for (int d = 1; d < 32; d <<= 1) {
        float tA = __shfl_up_sync(0xffffffffu, A, d);
        float tS = __shfl_up_sync(0xffffffffu, Sm, d);
        if (lane >= d) { A += tA; Sm += tS; }
    }
    if (lane == 31) { wsumA[warp] = A; wsumM[warp] = Sm; }
    __syncthreads();
    if (warp == 0) {
        float xA = wsumA[lane], xS = wsumM[lane];
        #pragma unroll
        for (int d = 1; d < 32; d <<= 1) {
            float tA = __shfl_up_sync(0xffffffffu, xA, d);
            float tS = __shfl_up_sync(0xffffffffu, xS, d);
            if (lane >= d) { xA += tA; xS += tS; }
        }
        wsumA[lane] = xA; wsumM[lane] = xS;
    }
    __syncthreads();
    if (warp > 0) { A += wsumA[warp-1]; Sm += wsumM[warp-1]; }

    float pre = (xq + sbq + __fdividef(A, Sm)) * inv_sqrt;
    spre[tid] = pre;
    smk[tid]  = mk;
    __syncthreads();

    // ---- phase 2: per-warp chunk reduce (cache phi in registers) ----
    float ph[32];
    float M = NEG_BIG, S = 0.f, V = 0.f;
    int p0 = warp * 32;
    #pragma unroll
    for (int i = 0; i < 32; i++) {
        int p = p0 + i;
        float pr = spre[p];
        float f  = g_phi[(size_t)(base + p)*32 + lane];
        ph[i] = f;
        float nM = fmaxf(M, pr);
        float cs = __expf(M - nM);
        float w  = __expf(pr - nM);
        S = S*cs + w;
        V = V*cs + w*f;
        M = nM;
    }
    if (lane == 0) { cM[warp] = M; cS[warp] = S; }
    cV[warp*33 + lane] = V;
    __syncthreads();

    // ---- phase 3: warp 0 exclusive scan over 32 chunk summaries ----
    if (warp == 0) {
        float eM = NEG_BIG, eS = 0.f, eV = 0.f;
        #pragma unroll
        for (int c = 0; c < 32; c++) {
            if (lane == 0) { pM[c] = eM; pS[c] = eS; }
            pV[c*33 + lane] = eV;
            float m2 = cM[c], s2 = cS[c], v2 = cV[c*33 + lane];
            float nM = fmaxf(eM, m2);
            float e1 = __expf(eM - nM);
            float e2 = __expf(m2 - nM);
            eS = eS*e1 + s2*e2;
            eV = eV*e1 + v2*e2;
            eM = nM;
        }
    }
    __syncthreads();

    // ---- phase 4: replay chunk seeded with exclusive prefix ----
    M = pM[warp]; S = pS[warp]; V = pV[warp*33 + lane];
    #pragma unroll
    for (int i = 0; i < 32; i++) {
        int p = p0 + i;
        float pr = spre[p];
        float nM = fmaxf(M, pr);
        float cs = __expf(M - nM);
        float w  = __expf(pr - nM);
        S = S*cs + w;
        V = V*cs + w*ph[i];
        M = nM;
        g_agg[(size_t)(base + p)*128 + h*32 + lane] = __fdividef(V, S) * smk[p];
    }
}

// ---------------------------------------------------------------- k_rho
// 512 threads: 128 tokens x 4 output-quarters. tok = tid>>2, q4 = tid&3.
#define RHO_PAD 132
#define HH_PAD  68
#define W1_BS   2056   // 128*16 + 8  (block stride per q4; ≡8 mod 32 → conflict-free)
#define W2_BS   1032   // 64*16 + 8
extern __shared__ float rho_smem[];
__global__ void __launch_bounds__(512) k_rho(
    const float* __restrict__ W1, const float* __restrict__ b1,
    const float* __restrict__ W2, const float* __restrict__ b2,
    const float* __restrict__ mask, float* __restrict__ out)
{
    float* sW1 = rho_smem;                  // 4 * W1_BS
    float* sW2 = sW1 + 4*W1_BS;             // 4 * W2_BS
    float* sA  = sW2 + 4*W2_BS;             // 128*RHO_PAD (reused as sHH)
    float* sb1 = sA  + 128*RHO_PAD;
    float* sb2 = sb1 + 64;
    float* sHH = sA;

    int tid  = threadIdx.x;
    int tok  = tid >> 2;
    int q4   = tid & 3;
    int tok0 = blockIdx.x * 128;

    // stage weights, q4-interleaved: sW1[q][k*16 + jj] = W1[k*64 + q*16 + jj]
    for (int i = tid; i < 128*64; i += 512) {
        int k = i >> 6, j = i & 63;
        sW1[(j>>4)*W1_BS + k*16 + (j&15)] = W1[i];
    }
    for (int i = tid; i < 64*64; i += 512) {
        int c = i >> 6, j = i & 63;
        sW2[(j>>4)*W2_BS + c*16 + (j&15)] = W2[i];
    }
    if (tid < 64) { sb1[tid] = b1[tid]; sb2[tid] = b2[tid]; }
    {
        const float4* src = (const float4*)(g_agg + (size_t)tok0*128);
        #pragma unroll 8
        for (int l4 = tid; l4 < 128*32; l4 += 512) {
            int tk = l4 >> 5, k4 = l4 & 31;
            ((float4*)(sA + tk*RHO_PAD))[k4] = src[l4];
        }
    }
    __syncthreads();

    // ---- layer 1: 16 outputs over K=128 ----
    float acc[16];
    #pragma unroll
    for (int j = 0; j < 16; j++) acc[j] = 0.f;
    const float4* rowA = (const float4*)(sA + tok*RHO_PAD);
    const float4* w1q  = (const float4*)(sW1 + q4*W1_BS);
    #pragma unroll 4
    for (int k4 = 0; k4 < 32; k4++) {
        float4 xv = rowA[k4];
        #pragma unroll
        for (int e = 0; e < 4; e++) {
            float s = (e==0)?xv.x:(e==1)?xv.y:(e==2)?xv.z:xv.w;
            int k = k4*4 + e;
            #pragma unroll
            for (int j4 = 0; j4 < 4; j4++) {
                float4 w = w1q[k*4 + j4];
                acc[j4*4+0] += s*w.x; acc[j4*4+1] += s*w.y;
                acc[j4*4+2] += s*w.z; acc[j4*4+3] += s*w.w;
            }
        }
    }
    float hh[16];
    #pragma unroll
    for (int j = 0; j < 16; j++) hh[j] = fmaxf(acc[j] + sb1[q4*16 + j], 0.f);

    __syncthreads();   // all layer-1 act reads done before overwrite
    {
        float4* rowH = (float4*)(sHH + tok*HH_PAD);
        #pragma unroll
        for (int j4 = 0; j4 < 4; j4++)
            rowH[q4*4 + j4] = make_float4(hh[j4*4+0], hh[j4*4+1], hh[j4*4+2], hh[j4*4+3]);
    }
    __syncthreads();

    // ---- layer 2: 16 outputs over K=64 ----
    float acc2[16];
    #pragma unroll
    for (int j = 0; j < 16; j++) acc2[j] = sb2[q4*16 + j];
    const float4* rowH = (const float4*)(sHH + tok*HH_PAD);
    const float4* w2q  = (const float4*)(sW2 + q4*W2_BS);
    #pragma unroll 4
    for (int c4 = 0; c4 < 16; c4++) {
        float4 xv = rowH[c4];
        #pragma unroll
        for (int e = 0; e < 4; e++) {
            float s = (e==0)?xv.x:(e==1)?xv.y:(e==2)?xv.z:xv.w;
            int c = c4*4 + e;
            #pragma unroll
            for (int j4 = 0; j4 < 4; j4++) {
                float4 w = w2q[c*4 + j4];
                acc2[j4*4+0] += s*w.x; acc2[j4*4+1] += s*w.y;
                acc2[j4*4+2] += s*w.z; acc2[j4*4+3] += s*w.w;
            }
        }
    }
    float mk = mask[tok0 + tok];
    float4* op = (float4*)(out + (size_t)(tok0 + tok)*64 + q4*16);
    #pragma unroll
    for (int j4 = 0; j4 < 4; j4++) {
        op[j4] = make_float4(fmaxf(acc2[j4*4+0],0.f)*mk, fmaxf(acc2[j4*4+1],0.f)*mk,
                             fmaxf(acc2[j4*4+2],0.f)*mk, fmaxf(acc2[j4*4+3],0.f)*mk);
    }
}

// ---------------------------------------------------------------- launch
extern "C" void kernel_launch(void* const* d_in, const int* in_sizes, int n_in,
                              void* d_out, int out_size) {
    (void)in_sizes; (void)n_in; (void)out_size;
    const float* times  = (const float*)d_in[0];
    const float* values = (const float*)d_in[1];
    const int*   meas   = (const int*)  d_in[2];
    const float* mask   = (const float*)d_in[3];
    const float* Wp1 = (const float*)d_in[4];  const float* bp1 = (const float*)d_in[5];
    const float* Wp2 = (const float*)d_in[6];  const float* bp2 = (const float*)d_in[7];
    const float* Wk  = (const float*)d_in[8];  const float* bk  = (const float*)d_in[9];
    const float* q   = (const float*)d_in[10];
    const float* Wf1 = (const float*)d_in[11]; const float* bf1 = (const float*)d_in[12];
    const float* Wf2 = (const float*)d_in[13]; const float* bf2 = (const float*)d_in[14];
    const float* Wr1 = (const float*)d_in[15]; const float* br1 = (const float*)d_in[16];
    const float* Wr2 = (const float*)d_in[17]; const float* br2 = (const float*)d_in[18];
    float* out = (float*)d_out;

    size_t rho_bytes = (4*W1_BS + 4*W2_BS + 128*RHO_PAD + 128) * sizeof(float);
    cudaFuncSetAttribute(k_rho, cudaFuncAttributeMaxDynamicSharedMemorySize, (int)rho_bytes);

    k_feat<<<128, 256>>>(times, values, meas, mask,
                         Wp1, bp1, Wp2, bp2, Wk, q, Wf1, bf1, Wf2, bf2);
    k_scan<<<BATCH*4, 1024>>>(mask, bk, q);
    k_rho<<<128, 512, rho_bytes>>>(Wr1, br1, Wr2, br2, mask, out);
}